// round 1
// baseline (speedup 1.0000x reference)
#include <cuda_runtime.h>
#include <cuda_bf16.h>
#include <mma.h>
#include <math.h>

using namespace nvcuda;

#define SEQ   64
#define EDIM  512
#define HDIM  1024
#define ADIM  64
#define VOCAB 50257
#define DECK  (EDIM + ADIM)   // 576
#define NB    128             // persistent LSTM blocks (must be <= SM count)
#define GT    512             // gemm threads per block

// ---------------- scratch (device globals: no allocation allowed) ----------------
__device__ __align__(128) float g_encX[SEQ * EDIM];
__device__ __align__(128) float g_decX[SEQ * DECK];
__device__ __align__(128) float g_encPre[SEQ * 4 * HDIM];
__device__ __align__(128) float g_decPre[SEQ * 4 * HDIM];
__device__ __align__(128) float g_h[2][HDIM];
__device__ __align__(128) float g_hs[SEQ * HDIM];
__device__ float g_logZ[SEQ];
__device__ unsigned g_bar_cnt;   // monotonic within one k_lstm launch; reset by k_prep

// ---------------- prep: embedding gathers, h0 zero, barrier reset ----------------
__global__ void k_prep(const int* __restrict__ seq, const int* __restrict__ dec,
                       const float* __restrict__ emb, const float* __restrict__ feats)
{
    const int b = blockIdx.x, tid = threadIdx.x;
    if (b < SEQ) {
        const float* er = emb + (size_t)seq[b] * EDIM;
        float* de = g_encX + b * EDIM;
        for (int i = tid; i < EDIM; i += blockDim.x) de[i] = er[i];
        const float* dr = emb + (size_t)dec[b] * EDIM;
        float* dd = g_decX + b * DECK;
        for (int i = tid; i < EDIM; i += blockDim.x) dd[i] = dr[i];
        for (int i = tid; i < ADIM; i += blockDim.x) dd[EDIM + i] = feats[i];
    } else {
        for (int i = tid; i < HDIM; i += blockDim.x) g_h[0][i] = 0.f;
        if (tid == 0) g_bar_cnt = 0u;
    }
}

// ---------------- generic tf32 GEMM: C[64,N] = A[64,K] @ Wrows[N,K]^T + bias -------
// Block computes a 64(m) x 64(n) tile; 16 warps in a 4x4 layout; k-chunk = 32.
__global__ __launch_bounds__(GT) void k_gemm(
    const float* __restrict__ A, const float* __restrict__ W,
    const float* __restrict__ b0, const float* __restrict__ b1,
    float* __restrict__ C, int K, int N, int doRelu)
{
    __shared__ __align__(16) float sbuf[4608];   // As[64][36] | Ws[64][36], reused as Cs[64][68]
    float* As = sbuf;
    float* Ws = sbuf + 64 * 36;

    const int tid = threadIdx.x;
    const int wid = tid >> 5;
    const int wm = wid >> 2, wn = wid & 3;
    const int n0 = blockIdx.x * 64;

    wmma::fragment<wmma::accumulator, 16, 16, 8, float> cf;
    wmma::fill_fragment(cf, 0.f);

    for (int kc = 0; kc < K; kc += 32) {
        #pragma unroll
        for (int idx = tid; idx < 64 * 32; idx += GT) {
            int m = idx >> 5, kk = idx & 31;
            As[m * 36 + kk] = A[(size_t)m * K + kc + kk];
        }
        #pragma unroll
        for (int idx = tid; idx < 64 * 32; idx += GT) {
            int n = idx >> 5, kk = idx & 31;
            int row = n0 + n;
            Ws[n * 36 + kk] = (row < N) ? W[(size_t)row * K + kc + kk] : 0.f;
        }
        __syncthreads();
        #pragma unroll
        for (int ks = 0; ks < 32; ks += 8) {
            wmma::fragment<wmma::matrix_a, 16, 16, 8, wmma::precision::tf32, wmma::row_major> af;
            wmma::fragment<wmma::matrix_b, 16, 16, 8, wmma::precision::tf32, wmma::col_major> bf;
            wmma::load_matrix_sync(af, As + wm * 16 * 36 + ks, 36);
            wmma::load_matrix_sync(bf, Ws + wn * 16 * 36 + ks, 36);
            #pragma unroll
            for (int i = 0; i < af.num_elements; i++) af.x[i] = wmma::__float_to_tf32(af.x[i]);
            #pragma unroll
            for (int i = 0; i < bf.num_elements; i++) bf.x[i] = wmma::__float_to_tf32(bf.x[i]);
            wmma::mma_sync(cf, af, bf, cf);
        }
        __syncthreads();
    }

    float* Cs = sbuf;  // reuse (all reads done; trailing __syncthreads above)
    wmma::store_matrix_sync(Cs + wm * 16 * 68 + wn * 16, cf, 68, wmma::mem_row_major);
    __syncthreads();
    for (int idx = tid; idx < 64 * 64; idx += GT) {
        int m = idx >> 6, n = idx & 63;
        int col = n0 + n;
        if (col < N) {
            float v = Cs[m * 68 + n] + b0[col] + (b1 ? b1[col] : 0.f);
            if (doRelu) v = fmaxf(v, 0.f);
            C[(size_t)m * N + col] = v;
        }
    }
}

// ---------------- persistent LSTM recurrence (128 steps, grid barrier per step) ----
// Block b owns hidden units [8b, 8b+8); warp w -> unit u = 8b + w.
// Lane l caches Whh[{i,f,g,o} rows of u][32l..32l+32) in registers (128 floats).
__global__ __launch_bounds__(256, 1) void k_lstm(
    const float* __restrict__ encWhh, const float* __restrict__ decWhh)
{
    const int tid  = threadIdx.x;
    const int warp = tid >> 5, lane = tid & 31;
    const int u = blockIdx.x * 8 + warp;

    float w[4][32];
    #pragma unroll
    for (int g = 0; g < 4; g++) {
        const float4* p = (const float4*)(encWhh + (size_t)(g * HDIM + u) * HDIM + lane * 32);
        #pragma unroll
        for (int i = 0; i < 8; i++) {
            float4 v = p[i];
            w[g][4*i+0]=v.x; w[g][4*i+1]=v.y; w[g][4*i+2]=v.z; w[g][4*i+3]=v.w;
        }
    }

    float c = 0.f;
    for (int s = 0; s < 128; s++) {
        const int cur = s & 1;

        float hv[32];
        const float4* hp = (const float4*)(&g_h[cur][0] + lane * 32);
        #pragma unroll
        for (int i = 0; i < 8; i++) {
            float4 v = __ldcg(hp + i);   // bypass L1: h changes every step
            hv[4*i]=v.x; hv[4*i+1]=v.y; hv[4*i+2]=v.z; hv[4*i+3]=v.w;
        }

        float a0 = 0.f, a1 = 0.f, a2 = 0.f, a3 = 0.f;
        #pragma unroll
        for (int kk = 0; kk < 32; kk++) {
            float h = hv[kk];
            a0 = fmaf(w[0][kk], h, a0);
            a1 = fmaf(w[1][kk], h, a1);
            a2 = fmaf(w[2][kk], h, a2);
            a3 = fmaf(w[3][kk], h, a3);
        }
        #pragma unroll
        for (int off = 16; off; off >>= 1) {
            a0 += __shfl_xor_sync(0xffffffffu, a0, off);
            a1 += __shfl_xor_sync(0xffffffffu, a1, off);
            a2 += __shfl_xor_sync(0xffffffffu, a2, off);
            a3 += __shfl_xor_sync(0xffffffffu, a3, off);
        }

        if (lane == 0) {
            const float* pre = (s < 64 ? g_encPre + s * 4 * HDIM
                                       : g_decPre + (s - 64) * 4 * HDIM) + u;
            float gi = a0 + pre[0];
            float gf = a1 + pre[HDIM];
            float gg = a2 + pre[2 * HDIM];
            float go = a3 + pre[3 * HDIM];
            float iv = 1.f / (1.f + expf(-gi));
            float fv = 1.f / (1.f + expf(-gf));
            float gv = tanhf(gg);
            float ov = 1.f / (1.f + expf(-go));
            c = fv * c + iv * gv;
            float hn = ov * tanhf(c);
            g_h[cur ^ 1][u] = hn;
            if (s >= 64) g_hs[(s - 64) * HDIM + u] = hn;
        }

        if (s == 63) {  // switch to decoder weights (reads immutable gmem; no sync needed)
            #pragma unroll
            for (int g = 0; g < 4; g++) {
                const float4* p = (const float4*)(decWhh + (size_t)(g * HDIM + u) * HDIM + lane * 32);
                #pragma unroll
                for (int i = 0; i < 8; i++) {
                    float4 v = p[i];
                    w[g][4*i]=v.x; w[g][4*i+1]=v.y; w[g][4*i+2]=v.z; w[g][4*i+3]=v.w;
                }
            }
        }

        if (s < 127) {  // grid barrier: monotonic counter, target = NB*(step+1)
            __threadfence();             // publish h writes (executed by writers too)
            __syncthreads();
            if (tid == 0) {
                atomicAdd(&g_bar_cnt, 1u);
                const unsigned target = (unsigned)(s + 1) * (unsigned)NB;
                while (*(volatile unsigned*)&g_bar_cnt < target) { }
            }
            __syncthreads();
        }
    }
}

// ---------------- log_softmax over relu'd logits already in d_out ----------------
__global__ void k_logz(const float* __restrict__ out)
{
    const int t = blockIdx.x, tid = threadIdx.x;
    const float* row = out + (size_t)t * VOCAB;
    float m = -1e30f, s = 0.f;
    for (int v = tid; v < VOCAB; v += 256) {
        float x = row[v];
        if (x > m) { s = s * expf(m - x) + 1.f; m = x; }
        else       { s += expf(x - m); }
    }
    __shared__ float sm[256], ss[256];
    sm[tid] = m; ss[tid] = s; __syncthreads();
    for (int o = 128; o; o >>= 1) {
        if (tid < o) {
            float m2 = sm[tid + o], s2 = ss[tid + o];
            float M = fmaxf(sm[tid], m2);
            ss[tid] = ss[tid] * expf(sm[tid] - M) + s2 * expf(m2 - M);
            sm[tid] = M;
        }
        __syncthreads();
    }
    if (tid == 0) g_logZ[t] = sm[0] + logf(ss[0]);
}

__global__ void k_sub(float* out)
{
    const int t = blockIdx.y;
    const int v = blockIdx.x * blockDim.x + threadIdx.x;
    if (v < VOCAB) out[(size_t)t * VOCAB + v] -= g_logZ[t];
}

// ---------------- launch ----------------
extern "C" void kernel_launch(void* const* d_in, const int* in_sizes, int n_in,
                              void* d_out, int out_size)
{
    const int*   seq   = (const int*)  d_in[0];
    const float* feats = (const float*)d_in[1];
    const int*   dec   = (const int*)  d_in[2];
    const float* emb   = (const float*)d_in[3];
    const float* eWih  = (const float*)d_in[4];
    const float* eWhh  = (const float*)d_in[5];
    const float* ebih  = (const float*)d_in[6];
    const float* ebhh  = (const float*)d_in[7];
    const float* dWih  = (const float*)d_in[8];
    const float* dWhh  = (const float*)d_in[9];
    const float* dbih  = (const float*)d_in[10];
    const float* dbhh  = (const float*)d_in[11];
    const float* linW  = (const float*)d_in[12];
    const float* linb  = (const float*)d_in[13];
    float* out = (float*)d_out;

    float *pEncX, *pDecX, *pEncPre, *pDecPre, *pHs;
    cudaGetSymbolAddress((void**)&pEncX,   g_encX);
    cudaGetSymbolAddress((void**)&pDecX,   g_decX);
    cudaGetSymbolAddress((void**)&pEncPre, g_encPre);
    cudaGetSymbolAddress((void**)&pDecPre, g_decPre);
    cudaGetSymbolAddress((void**)&pHs,     g_hs);

    k_prep<<<SEQ + 1, 256>>>(seq, dec, emb, feats);
    k_gemm<<<4 * HDIM / 64, GT>>>(pEncX, eWih, ebih, ebhh, pEncPre, EDIM, 4 * HDIM, 0);
    k_gemm<<<4 * HDIM / 64, GT>>>(pDecX, dWih, dbih, dbhh, pDecPre, DECK, 4 * HDIM, 0);
    k_lstm<<<NB, 256>>>(eWhh, dWhh);
    k_gemm<<<(VOCAB + 63) / 64, GT>>>(pHs, linW, linb, nullptr, out, HDIM, VOCAB, 1);
    k_logz<<<SEQ, 256>>>(out);
    k_sub<<<dim3((VOCAB + 255) / 256, SEQ), 256>>>(out);
}

// round 4
// speedup vs baseline: 2.6260x; 2.6260x over previous
#include <cuda_runtime.h>
#include <cuda_bf16.h>
#include <mma.h>
#include <math.h>

using namespace nvcuda;

#define SEQ   64
#define EDIM  512
#define HDIM  1024
#define ADIM  64
#define VOCAB 50257
#define DECK  (EDIM + ADIM)   // 576
#define NB    128             // persistent LSTM blocks (<= SM count, 1 wave)

// ---------------- scratch (device globals; allocation is forbidden) ----------------
__device__ __align__(128) float g_encX[SEQ * EDIM];
__device__ __align__(128) float g_decX[SEQ * DECK];
__device__ __align__(128) float g_encPre[SEQ * 4 * HDIM];
__device__ __align__(128) float g_decPre[SEQ * 4 * HDIM];
__device__ __align__(128) float g_hs[SEQ * HDIM];
// double-buffered h exchange: [parity][block][ 0..7 = h values, 8 = step tag ]
__device__ __align__(128) float g_hline[2][NB][32];

// ---------------- prep: embedding gathers + h-exchange reset -----------------------
__global__ void k_prep(const int* __restrict__ seq, const int* __restrict__ dec,
                       const float* __restrict__ emb, const float* __restrict__ feats)
{
    const int b = blockIdx.x, tid = threadIdx.x;
    if (b < SEQ) {
        const float* er = emb + (size_t)seq[b] * EDIM;
        float* de = g_encX + b * EDIM;
        for (int i = tid; i < EDIM; i += blockDim.x) de[i] = er[i];
        const float* dr = emb + (size_t)dec[b] * EDIM;
        float* dd = g_decX + b * DECK;
        for (int i = tid; i < EDIM; i += blockDim.x) dd[i] = dr[i];
        for (int i = tid; i < ADIM; i += blockDim.x) dd[EDIM + i] = feats[i];
    } else {
        float* p = &g_hline[0][0][0];
        for (int i = tid; i < 2 * NB * 32; i += blockDim.x) p[i] = 0.f;
    }
}

// ---------------- tf32 GEMM: C[64,N] = A[64,K] @ W[N,K]^T + bias, 2-stage cp.async --
#define GT 512
#define BK 32
#define APAD 36

__device__ __forceinline__ void cpasync16(void* dst, const void* src) {
    unsigned d = (unsigned)__cvta_generic_to_shared(dst);
    asm volatile("cp.async.cg.shared.global [%0], [%1], 16;" :: "r"(d), "l"(src));
}

__global__ __launch_bounds__(GT) void k_gemm(
    const float* __restrict__ A, const float* __restrict__ W,
    const float* __restrict__ b0, const float* __restrict__ b1,
    float* __restrict__ C, int K, int N, int doRelu)
{
    extern __shared__ float smem[];
    float* As = smem;                  // [2][64][APAD]
    float* Ws = smem + 2 * 64 * APAD;  // [2][128][APAD]

    const int tid = threadIdx.x;
    const int wid = tid >> 5;
    const int wm = wid >> 2, wn = wid & 3;
    const int n0 = blockIdx.x * 128;
    const int nc = K / BK;

    wmma::fragment<wmma::accumulator, 16, 16, 8, float> cf[2];
    wmma::fill_fragment(cf[0], 0.f);
    wmma::fill_fragment(cf[1], 0.f);

    auto load_stage = [&](int stg, int c) {
        const int kc = c * BK;
        {
            int r = tid >> 3, ch = tid & 7;
            cpasync16(As + stg * 64 * APAD + r * APAD + ch * 4,
                      A + (size_t)r * K + kc + ch * 4);
        }
        #pragma unroll
        for (int it = 0; it < 2; it++) {
            int t = tid + it * GT;
            int r = t >> 3, ch = t & 7;
            int rg = n0 + r; if (rg > N - 1) rg = N - 1;   // clamp; masked at store
            cpasync16(Ws + stg * 128 * APAD + r * APAD + ch * 4,
                      W + (size_t)rg * K + kc + ch * 4);
        }
        asm volatile("cp.async.commit_group;");
    };

    load_stage(0, 0);
    for (int c = 0; c < nc; c++) {
        const int cur = c & 1;
        if (c + 1 < nc) { load_stage(cur ^ 1, c + 1); asm volatile("cp.async.wait_group 1;"); }
        else            { asm volatile("cp.async.wait_group 0;"); }
        __syncthreads();
        const float* Ab = As + cur * 64 * APAD + wm * 16 * APAD;
        const float* Wb = Ws + cur * 128 * APAD + wn * 32 * APAD;
        #pragma unroll
        for (int ks = 0; ks < BK; ks += 8) {
            wmma::fragment<wmma::matrix_a, 16, 16, 8, wmma::precision::tf32, wmma::row_major> af;
            wmma::load_matrix_sync(af, Ab + ks, APAD);
            #pragma unroll
            for (int i = 0; i < af.num_elements; i++) af.x[i] = wmma::__float_to_tf32(af.x[i]);
            #pragma unroll
            for (int nf = 0; nf < 2; nf++) {
                wmma::fragment<wmma::matrix_b, 16, 16, 8, wmma::precision::tf32, wmma::col_major> bf;
                wmma::load_matrix_sync(bf, Wb + nf * 16 * APAD + ks, APAD);
                #pragma unroll
                for (int i = 0; i < bf.num_elements; i++) bf.x[i] = wmma::__float_to_tf32(bf.x[i]);
                wmma::mma_sync(cf[nf], af, bf, cf[nf]);
            }
        }
        __syncthreads();
    }

    float* Cs = smem;  // 64 x 132 (reuse; trailing sync above)
    wmma::store_matrix_sync(Cs + wm * 16 * 132 + wn * 32 +  0, cf[0], 132, wmma::mem_row_major);
    wmma::store_matrix_sync(Cs + wm * 16 * 132 + wn * 32 + 16, cf[1], 132, wmma::mem_row_major);
    __syncthreads();
    for (int idx = tid; idx < 64 * 128; idx += GT) {
        int m = idx >> 7, n = idx & 127;
        int col = n0 + n;
        if (col < N) {
            float v = Cs[m * 132 + n] + b0[col] + (b1 ? b1[col] : 0.f);
            if (doRelu) v = fmaxf(v, 0.f);
            C[(size_t)m * N + col] = v;
        }
    }
}

// ---------------- persistent LSTM recurrence: data-flow sync, no global barrier -----
// Block b owns units [8b,8b+8); warp w -> unit u=8b+w; lane l covers k = 4l+128j.
// Grid = 128 blocks at occupancy 1 -> all co-resident in wave 1 (>=128 SMs).
__global__ __launch_bounds__(256, 1) void k_lstm(
    const float* __restrict__ encWhh, const float* __restrict__ decWhh)
{
    __shared__ float h_sh[HDIM];
    const int tid  = threadIdx.x;
    const int warp = tid >> 5, lane = tid & 31;
    const int bid  = blockIdx.x;
    const int u = bid * 8 + warp;

    float w0[32], w1[32], w2[32], w3[32];
    {
        const float* base = encWhh + (size_t)u * HDIM + 4 * lane;
        #pragma unroll
        for (int j = 0; j < 8; j++) {
            float4 v;
            v = *(const float4*)(base + 0 * HDIM * HDIM + 128 * j); w0[4*j]=v.x; w0[4*j+1]=v.y; w0[4*j+2]=v.z; w0[4*j+3]=v.w;
            v = *(const float4*)(base + 1 * HDIM * HDIM + 128 * j); w1[4*j]=v.x; w1[4*j+1]=v.y; w1[4*j+2]=v.z; w1[4*j+3]=v.w;
            v = *(const float4*)(base + 2 * HDIM * HDIM + 128 * j); w2[4*j]=v.x; w2[4*j+1]=v.y; w2[4*j+2]=v.z; w2[4*j+3]=v.w;
            v = *(const float4*)(base + 3 * HDIM * HDIM + 128 * j); w3[4*j]=v.x; w3[4*j+1]=v.y; w3[4*j+2]=v.z; w3[4*j+3]=v.w;
        }
    }

    float c = 0.f;
    for (int s = 0; s < 128; s++) {
        // pre-gate fetch (independent of h); lane g in 0..3 takes gate g
        const float* pre = (s < 64 ? g_encPre + s * 4 * HDIM
                                   : g_decPre + (s - 64) * 4 * HDIM) + u;
        float pg = 0.f;
        if (lane < 4) pg = pre[lane * HDIM];

        // gather h from exchange lines (read buffer = (s+1)&1, poll tag >= s)
        const int rb = (s + 1) & 1;
        if (tid < NB) {
            const unsigned* tp = (const unsigned*)&g_hline[rb][tid][8];
            unsigned v;
            asm volatile("ld.acquire.gpu.global.u32 %0, [%1];" : "=r"(v) : "l"(tp) : "memory");
            if (v < (unsigned)s) {
                int spins = 0;
                do {
                    if (++spins > 64) __nanosleep(64);   // backoff: keep L2 calm
                    asm volatile("ld.acquire.gpu.global.u32 %0, [%1];" : "=r"(v) : "l"(tp) : "memory");
                } while (v < (unsigned)s);
            }
            const float4* src = (const float4*)&g_hline[rb][tid][0];
            float4 a = __ldcg(src), b2 = __ldcg(src + 1);
            *(float4*)&h_sh[8 * tid]     = a;
            *(float4*)&h_sh[8 * tid + 4] = b2;
        }
        __syncthreads();

        float a0 = 0.f, a1 = 0.f, a2 = 0.f, a3 = 0.f;
        #pragma unroll
        for (int j = 0; j < 8; j++) {
            float4 hv = *(const float4*)&h_sh[128 * j + 4 * lane];
            a0 = fmaf(w0[4*j], hv.x, a0); a0 = fmaf(w0[4*j+1], hv.y, a0); a0 = fmaf(w0[4*j+2], hv.z, a0); a0 = fmaf(w0[4*j+3], hv.w, a0);
            a1 = fmaf(w1[4*j], hv.x, a1); a1 = fmaf(w1[4*j+1], hv.y, a1); a1 = fmaf(w1[4*j+2], hv.z, a1); a1 = fmaf(w1[4*j+3], hv.w, a1);
            a2 = fmaf(w2[4*j], hv.x, a2); a2 = fmaf(w2[4*j+1], hv.y, a2); a2 = fmaf(w2[4*j+2], hv.z, a2); a2 = fmaf(w2[4*j+3], hv.w, a2);
            a3 = fmaf(w3[4*j], hv.x, a3); a3 = fmaf(w3[4*j+1], hv.y, a3); a3 = fmaf(w3[4*j+2], hv.z, a3); a3 = fmaf(w3[4*j+3], hv.w, a3);
        }
        #pragma unroll
        for (int off = 16; off; off >>= 1) {
            a0 += __shfl_xor_sync(0xffffffffu, a0, off);
            a1 += __shfl_xor_sync(0xffffffffu, a1, off);
            a2 += __shfl_xor_sync(0xffffffffu, a2, off);
            a3 += __shfl_xor_sync(0xffffffffu, a3, off);
        }
        // gate activations: lanes 0..3 compute i,f,g,o in parallel, gather on lane 0
        {
            float ga = (lane == 1) ? a1 : (lane == 2) ? a2 : (lane == 3) ? a3 : a0;
            float gv2 = ga + pg;
            float act = (lane == 2) ? tanhf(gv2) : 1.f / (1.f + expf(-gv2));
            float iv = __shfl_sync(0xffffffffu, act, 0);
            float fv = __shfl_sync(0xffffffffu, act, 1);
            float gg = __shfl_sync(0xffffffffu, act, 2);
            float ov = __shfl_sync(0xffffffffu, act, 3);
            if (lane == 0) {
                c = fv * c + iv * gg;
                float hn = ov * tanhf(c);
                g_hline[s & 1][bid][warp] = hn;         // ordered by bar.sync + release below
                if (s >= 64) g_hs[(s - 64) * HDIM + u] = hn;
            }
        }

        if (s == 63) {  // switch to decoder recurrent weights (immutable gmem)
            const float* base = decWhh + (size_t)u * HDIM + 4 * lane;
            #pragma unroll
            for (int j = 0; j < 8; j++) {
                float4 v;
                v = *(const float4*)(base + 0 * HDIM * HDIM + 128 * j); w0[4*j]=v.x; w0[4*j+1]=v.y; w0[4*j+2]=v.z; w0[4*j+3]=v.w;
                v = *(const float4*)(base + 1 * HDIM * HDIM + 128 * j); w1[4*j]=v.x; w1[4*j+1]=v.y; w1[4*j+2]=v.z; w1[4*j+3]=v.w;
                v = *(const float4*)(base + 2 * HDIM * HDIM + 128 * j); w2[4*j]=v.x; w2[4*j+1]=v.y; w2[4*j+2]=v.z; w2[4*j+3]=v.w;
                v = *(const float4*)(base + 3 * HDIM * HDIM + 128 * j); w3[4*j]=v.x; w3[4*j+1]=v.y; w3[4*j+2]=v.z; w3[4*j+3]=v.w;
            }
        }

        __syncthreads();   // orders this block's 8 h-stores before the release
        if (tid == 0) {
            unsigned* tp = (unsigned*)&g_hline[s & 1][bid][8];
            unsigned tv = (unsigned)(s + 1);
            asm volatile("st.release.gpu.global.u32 [%0], %1;" :: "l"(tp), "r"(tv) : "memory");
        }
    }
}

// ---------------- fused log-softmax: logZ + subtract (row stays hot in L2) ---------
__global__ __launch_bounds__(1024) void k_softmax(float* __restrict__ out)
{
    const int t = blockIdx.x, tid = threadIdx.x;
    float* row = out + (size_t)t * VOCAB;
    float m = -1e30f, s = 0.f;
    for (int v = tid; v < VOCAB; v += 1024) {
        float x = row[v];
        if (x > m) { s = s * expf(m - x) + 1.f; m = x; }
        else       { s += expf(x - m); }
    }
    #pragma unroll
    for (int off = 16; off; off >>= 1) {
        float m2 = __shfl_xor_sync(0xffffffffu, m, off);
        float s2 = __shfl_xor_sync(0xffffffffu, s, off);
        float M = fmaxf(m, m2);
        s = s * expf(m - M) + s2 * expf(m2 - M);
        m = M;
    }
    __shared__ float sm[32], ss[32], sz[1];
    if ((tid & 31) == 0) { sm[tid >> 5] = m; ss[tid >> 5] = s; }
    __syncthreads();
    if (tid < 32) {
        m = sm[tid]; s = ss[tid];
        #pragma unroll
        for (int off = 16; off; off >>= 1) {
            float m2 = __shfl_xor_sync(0xffffffffu, m, off);
            float s2 = __shfl_xor_sync(0xffffffffu, s, off);
            float M = fmaxf(m, m2);
            s = s * expf(m - M) + s2 * expf(m2 - M);
            m = M;
        }
        if (tid == 0) sz[0] = m + logf(s);
    }
    __syncthreads();
    float lz = sz[0];
    for (int v = tid; v < VOCAB; v += 1024) row[v] -= lz;
}

// ---------------- launch ----------------
extern "C" void kernel_launch(void* const* d_in, const int* in_sizes, int n_in,
                              void* d_out, int out_size)
{
    const int*   seq   = (const int*)  d_in[0];
    const float* feats = (const float*)d_in[1];
    const int*   dec   = (const int*)  d_in[2];
    const float* emb   = (const float*)d_in[3];
    const float* eWih  = (const float*)d_in[4];
    const float* eWhh  = (const float*)d_in[5];
    const float* ebih  = (const float*)d_in[6];
    const float* ebhh  = (const float*)d_in[7];
    const float* dWih  = (const float*)d_in[8];
    const float* dWhh  = (const float*)d_in[9];
    const float* dbih  = (const float*)d_in[10];
    const float* dbhh  = (const float*)d_in[11];
    const float* linW  = (const float*)d_in[12];
    const float* linb  = (const float*)d_in[13];
    float* out = (float*)d_out;

    float *pEncX, *pDecX, *pEncPre, *pDecPre, *pHs;
    cudaGetSymbolAddress((void**)&pEncX,   g_encX);
    cudaGetSymbolAddress((void**)&pDecX,   g_decX);
    cudaGetSymbolAddress((void**)&pEncPre, g_encPre);
    cudaGetSymbolAddress((void**)&pDecPre, g_decPre);
    cudaGetSymbolAddress((void**)&pHs,     g_hs);

    const int smemB = 2 * (64 + 128) * APAD * 4;   // 55296 B
    cudaFuncSetAttribute(k_gemm, cudaFuncAttributeMaxDynamicSharedMemorySize, smemB);

    k_prep<<<SEQ + 1, 256>>>(seq, dec, emb, feats);
    k_gemm<<<4 * HDIM / 128, GT, smemB>>>(pEncX, eWih, ebih, ebhh, pEncPre, EDIM, 4 * HDIM, 0);
    k_gemm<<<4 * HDIM / 128, GT, smemB>>>(pDecX, dWih, dbih, dbhh, pDecPre, DECK, 4 * HDIM, 0);
    k_lstm<<<NB, 256>>>(eWhh, dWhh);
    k_gemm<<<(VOCAB + 127) / 128, GT, smemB>>>(pHs, linW, linb, nullptr, out, HDIM, VOCAB, 1);
    k_softmax<<<SEQ, 1024>>>(out);
}